// round 13
// baseline (speedup 1.0000x reference)
#include <cuda_runtime.h>

#define N 8192
#define NW 256            // 32-bit words per mask row (8192/32)
#define MIN_SCORE 0.3f
#define NMS_THR 0.3f
#define MAX_OUT 256

// scratch (no allocations allowed; zero-initialized at module load)
__device__ int      g_order[N];
__device__ float    g_ssort[N];
__device__ unsigned g_partial[8][N];
__device__ float4   g_sxyxy[N];       // sorted-order xyxy
__device__ float    g_sarea[N];       // sorted-order area
__device__ unsigned g_valid[NW];      // score >= MIN_SCORE, by sorted rank
__device__ unsigned g_mask[N][NW];    // suppression matrix, 8MB (L2-resident)

// ---------------------------------------------------------------------------
// Rank sort, stage 1: partial ranks over a 1024-wide j-tile per block.
// rank(i) = #{j<i : s_j >= s_i} + #{j>=i : s_j > s_i}
// (exactly matches stable argsort(-s): ties broken by ascending index)
// grid (64, 8) x 128 threads.  Block (0,0) also re-zeroes g_valid each launch.
// ---------------------------------------------------------------------------
__global__ __launch_bounds__(128) void rank_partial_kernel(const float* __restrict__ score)
{
    __shared__ float sh[1024];
    const int jlo = blockIdx.y << 10;
    for (int r = threadIdx.x; r < 1024; r += 128) sh[r] = score[jlo + r];
    if (blockIdx.x == 0 && blockIdx.y == 0) {
        g_valid[threadIdx.x] = 0;
        g_valid[threadIdx.x + 128] = 0;
    }
    __syncthreads();

    const int i = blockIdx.x * 128 + threadIdx.x;
    const float si = score[i];

    int m = i - jlo;                    // local j < m  <=>  global j < i
    m = m < 0 ? 0 : (m > 1024 ? 1024 : m);

    int cnt = 0;
    const float4* sh4 = reinterpret_cast<const float4*>(sh);

    const int m4 = m >> 2;
    for (int q = 0; q < m4; ++q) {
        float4 v = sh4[q];
        cnt += (v.x >= si) + (v.y >= si) + (v.z >= si) + (v.w >= si);
    }
    for (int r = m4 << 2; r < m; ++r) cnt += (sh[r] >= si);

    const int q0 = (m + 3) >> 2;
    int rend = q0 << 2; if (rend > 1024) rend = 1024;
    for (int r = m; r < rend; ++r) cnt += (sh[r] > si);
    for (int q = q0; q < 256; ++q) {
        float4 v = sh4[q];
        cnt += (v.x > si) + (v.y > si) + (v.z > si) + (v.w > si);
    }

    g_partial[blockIdx.y][i] = (unsigned)cnt;
}

// ---------------------------------------------------------------------------
// Stage 2: combine partials; scatter index/score/xyxy/area into sorted rank;
// build the valid bitmask.
// ---------------------------------------------------------------------------
__global__ __launch_bounds__(256) void rank_scatter_kernel(const float* __restrict__ score,
                                                           const float* __restrict__ box)
{
    const int i = blockIdx.x * 256 + threadIdx.x;
    unsigned rank = 0;
#pragma unroll
    for (int k = 0; k < 8; ++k) rank += g_partial[k][i];

    const float s = score[i];
    g_order[rank] = i;
    g_ssort[rank] = s;

    const float4 b = *reinterpret_cast<const float4*>(box + (size_t)i * 16);
    const float hw = __fmul_rn(b.z, 0.5f);
    const float hh = __fmul_rn(b.w, 0.5f);
    const float x1 = __fsub_rn(b.x, hw);
    const float y1 = __fsub_rn(b.y, hh);
    const float x2 = __fadd_rn(b.x, hw);
    const float y2 = __fadd_rn(b.y, hh);
    g_sxyxy[rank] = make_float4(x1, y1, x2, y2);
    g_sarea[rank] = __fmul_rn(__fsub_rn(x2, x1), __fsub_rn(y2, y1));

    if (s >= MIN_SCORE) atomicOr(&g_valid[rank >> 5], 1u << (rank & 31));
}

// ---------------------------------------------------------------------------
// Suppression matrix: g_mask[i] bit j = (IoU(i,j) > thr).
// Lower-triangle words may be stale/unwritten — the scan provably never
// consults them (only j>i bits are used; garbage OR'd into acc lands strictly
// below the monotone frontier).
// ---------------------------------------------------------------------------
__global__ __launch_bounds__(256) void mask_kernel()
{
    const int cc = blockIdx.x;             // col chunk of 1024
    const int rb = blockIdx.y;             // row block of 256
    if ((cc + 1) * 1024 <= rb * 256) return;   // whole chunk strictly below diag

    __shared__ float4 sxy[1024];
    __shared__ float  sar[1024];
    const int jbase = cc << 10;
    for (int r = threadIdx.x; r < 1024; r += 256) {
        sxy[r] = g_sxyxy[jbase + r];
        sar[r] = g_sarea[jbase + r];
    }
    __syncthreads();

    const int w = threadIdx.x >> 5, lane = threadIdx.x & 31;
    const int rowbase = (rb << 8) + (w << 5);
    const int i = rowbase + lane;
    const float4 bi = g_sxyxy[i];
    const float  ai = g_sarea[i];

    int jw0 = (rowbase - jbase) >> 5;      // words with all j < every lane's i
    if (jw0 < 0) jw0 = 0;

    for (int jw = jw0; jw < 32; ++jw) {
        unsigned word = 0;
#pragma unroll 8
        for (int b = 0; b < 32; ++b) {
            const int jl = (jw << 5) + b;
            const float4 bj = sxy[jl];
            const float  aj = sar[jl];
            const float ltx = fmaxf(bi.x, bj.x);
            const float lty = fmaxf(bi.y, bj.y);
            const float rbx = fminf(bi.z, bj.z);
            const float rby = fminf(bi.w, bj.w);
            const float ww = fmaxf(__fsub_rn(rbx, ltx), 0.0f);
            const float hh = fmaxf(__fsub_rn(rby, lty), 0.0f);
            const float inter = __fmul_rn(ww, hh);
            const float den =
                __fadd_rn(__fsub_rn(__fadd_rn(ai, aj), inter), 1e-9f);
            if (inter > __fmul_rn(NMS_THR, den)) word |= (1u << b);
        }
        g_mask[i][(cc << 5) + jw] = word;
    }
}

// ---------------------------------------------------------------------------
// Candidate-batch greedy scan + output (256 threads, 1 block).
// Thread t owns suppression word t (register acc). Per batch:
//   1. warp 0 enumerates the 32 lowest alive ranks (the next candidates)
//   2. all threads fetch exactly those 32 mask rows into smem (32KB, MLP 32)
//   3. warp 0 extracts the 32x32 candidate sub-matrix (conflict-free banking)
//      and resolves exact greedy (REDUX.OR fast path; serial ffs fallback)
//   4. all threads OR accepted rows' word t into acc
// Every candidate leaves the alive set each batch -> ~kept/32 batches total.
// ---------------------------------------------------------------------------
__global__ __launch_bounds__(256, 1) void scan_out_kernel(const float* __restrict__ box,
                                                          float* __restrict__ out)
{
    __shared__ unsigned s_rows[32][257];   // stride 257 => banks (k+t)%32
    __shared__ unsigned s_alive[NW];
    __shared__ int s_cand[32];
    __shared__ unsigned s_keptmask;
    __shared__ int s_ncand, s_nk, s_wstart, s_stop;
    __shared__ int s_kept[MAX_OUT];

    const int t = threadIdx.x;
    const unsigned FULL = 0xffffffffu;

    unsigned acc = 0;
    const unsigned validw = g_valid[t];
    if (t == 0) { s_nk = 0; s_wstart = 0; s_stop = 0; }
    __syncthreads();

    while (true) {
        s_alive[t] = validw & ~acc;
        __syncthreads();

        // ---- 1. find up to 32 lowest alive ranks (warp 0)
        if (t < 32) {
            int cnt = 0;
            for (int wg = s_wstart >> 5; wg < 8 && cnt < 32; ++wg) {
                unsigned w = s_alive[(wg << 5) + t];
                unsigned bal = __ballot_sync(FULL, w != 0);
                while (bal && cnt < 32) {
                    const int l = __ffs(bal) - 1;
                    unsigned wl = __shfl_sync(FULL, w, l);
                    while (wl && cnt < 32) {
                        const int b = __ffs(wl) - 1;
                        wl &= wl - 1u;
                        if (t == 0) s_cand[cnt] = (((wg << 5) + l) << 5) + b;
                        ++cnt;
                    }
                    if (wl) break;
                    bal &= ~(1u << l);
                }
            }
            if (t == 0) s_ncand = cnt;
        }
        __syncthreads();

        const int ncand = s_ncand;
        if (ncand == 0) break;

        // ---- 2. fetch candidate rows (coalesced across t, independent -> MLP)
        for (int k = 0; k < ncand; ++k)
            s_rows[k][t] = g_mask[s_cand[k]][t];
        __syncthreads();

        // ---- 3. resolve (warp 0)
        if (t < 32) {
            unsigned B = 0;                       // bit j: cand t suppresses cand j
            if (t < ncand) {
                for (int j = 0; j < ncand; ++j) {
                    const int r = s_cand[j];
                    B |= ((s_rows[t][r >> 5] >> (r & 31)) & 1u) << j;
                }
            }
            const unsigned candmask = (ncand == 32) ? FULL : ((1u << ncand) - 1u);
            const unsigned above = ~((2u << t) - 1u);      // t=31 -> 0
            const unsigned bad = __reduce_or_sync(FULL, B & above);

            unsigned kept;
            if (bad == 0) {
                kept = candmask;                  // fast path: mutually disjoint
            } else {
                unsigned cur = candmask; kept = 0;
                while (cur) {                     // exact serial greedy
                    const int i = __ffs(cur) - 1;
                    kept |= 1u << i;
                    const unsigned row = __shfl_sync(FULL, B, i);
                    cur &= ~(1u << i);
                    cur &= ~row;
                }
            }

            int nk = s_nk;
            if ((kept >> t) & 1u) {
                const int pos = nk + __popc(kept & ((1u << t) - 1u));
                if (pos < MAX_OUT) s_kept[pos] = s_cand[t];
            }
            nk += __popc(kept);
            if (nk >= MAX_OUT) { nk = MAX_OUT; if (t == 0) s_stop = 1; }
            if (t == 0) {
                s_nk = nk;
                s_keptmask = kept;
                s_wstart = s_cand[ncand - 1] >> 5;   // monotone frontier
            }
        }
        __syncthreads();

        if (s_stop) break;                        // uniform

        // ---- 4. apply accepted rows (conflict-free LDS, banks (k+t)%32)
        unsigned km = s_keptmask, orv = 0;
        while (km) {
            const int k = __ffs(km) - 1;
            km &= km - 1u;
            orv |= s_rows[k][t];
        }
        acc |= orv;
        // explicitly retire accepted candidates (self-bit safety for
        // degenerate zero-area boxes whose self-IoU is 0)
        unsigned km2 = s_keptmask;
        while (km2) {
            const int k = __ffs(km2) - 1;
            km2 &= km2 - 1u;
            const int r = s_cand[k];
            if ((r >> 5) == t) acc |= 1u << (r & 31);
        }
        // loop-top barrier orders this against the next batch
    }
    __syncthreads();

    const int nkf = s_nk;

    // Output: [score(256) | box(256x16) | valid(256)] as float32.
    float4 vb0 = make_float4(0.f, 0.f, 0.f, 0.f), vb1 = vb0, vb2 = vb0, vb3 = vb0;
    float sc = 0.0f, vl = 0.0f;
    if (t < nkf) {
        const int si = s_kept[t];
        const int orig = g_order[si];
        const float4* bp = reinterpret_cast<const float4*>(box + (size_t)orig * 16);
        vb0 = bp[0]; vb1 = bp[1]; vb2 = bp[2]; vb3 = bp[3];
        sc = g_ssort[si];
        vl = 1.0f;
    }
    float4* op = reinterpret_cast<float4*>(out + 256 + t * 16);
    op[0] = vb0; op[1] = vb1; op[2] = vb2; op[3] = vb3;
    out[t] = sc;
    out[4352 + t] = vl;
}

extern "C" void kernel_launch(void* const* d_in, const int* in_sizes, int n_in,
                              void* d_out, int out_size)
{
    (void)in_sizes; (void)n_in; (void)out_size;
    const float* score = (const float*)d_in[0];
    const float* box   = (const float*)d_in[1];
    float* out = (float*)d_out;

    rank_partial_kernel<<<dim3(64, 8), 128>>>(score);
    rank_scatter_kernel<<<32, 256>>>(score, box);
    mask_kernel<<<dim3(8, 32), 256>>>();
    scan_out_kernel<<<1, 256>>>(box, out);
}

// round 14
// speedup vs baseline: 1.5419x; 1.5419x over previous
#include <cuda_runtime.h>

#define N 8192
#define NW 256            // 32-bit words per mask row (8192/32)
#define MIN_SCORE 0.3f
#define NMS_THR 0.3f
#define MAX_OUT 256

// scratch (no allocations allowed; zero-initialized at module load)
__device__ int      g_order[N];
__device__ float    g_ssort[N];
__device__ unsigned g_partial[8][N];
__device__ float4   g_sxyxy[N];       // sorted-order xyxy
__device__ float    g_sarea[N];       // sorted-order area
__device__ unsigned g_valid[NW];      // score >= MIN_SCORE, by sorted rank
__device__ unsigned g_mask[N][NW];    // suppression matrix, 8MB (L2-resident)

// ---------------------------------------------------------------------------
// Rank sort, stage 1: partial ranks over a 1024-wide j-tile per block.
// rank(i) = #{j<i : s_j >= s_i} + #{j>=i : s_j > s_i}
// (exactly matches stable argsort(-s): ties broken by ascending index)
// ---------------------------------------------------------------------------
__global__ __launch_bounds__(128) void rank_partial_kernel(const float* __restrict__ score)
{
    __shared__ float sh[1024];
    const int jlo = blockIdx.y << 10;
    for (int r = threadIdx.x; r < 1024; r += 128) sh[r] = score[jlo + r];
    if (blockIdx.x == 0 && blockIdx.y == 0) {
        g_valid[threadIdx.x] = 0;
        g_valid[threadIdx.x + 128] = 0;
    }
    __syncthreads();

    const int i = blockIdx.x * 128 + threadIdx.x;
    const float si = score[i];

    int m = i - jlo;                    // local j < m  <=>  global j < i
    m = m < 0 ? 0 : (m > 1024 ? 1024 : m);

    int cnt = 0;
    const float4* sh4 = reinterpret_cast<const float4*>(sh);

    const int m4 = m >> 2;
    for (int q = 0; q < m4; ++q) {
        float4 v = sh4[q];
        cnt += (v.x >= si) + (v.y >= si) + (v.z >= si) + (v.w >= si);
    }
    for (int r = m4 << 2; r < m; ++r) cnt += (sh[r] >= si);

    const int q0 = (m + 3) >> 2;
    int rend = q0 << 2; if (rend > 1024) rend = 1024;
    for (int r = m; r < rend; ++r) cnt += (sh[r] > si);
    for (int q = q0; q < 256; ++q) {
        float4 v = sh4[q];
        cnt += (v.x > si) + (v.y > si) + (v.z > si) + (v.w > si);
    }

    g_partial[blockIdx.y][i] = (unsigned)cnt;
}

// ---------------------------------------------------------------------------
// Stage 2: combine partials; scatter index/score/xyxy/area into sorted rank;
// build the valid bitmask.
// ---------------------------------------------------------------------------
__global__ __launch_bounds__(256) void rank_scatter_kernel(const float* __restrict__ score,
                                                           const float* __restrict__ box)
{
    const int i = blockIdx.x * 256 + threadIdx.x;
    unsigned rank = 0;
#pragma unroll
    for (int k = 0; k < 8; ++k) rank += g_partial[k][i];

    const float s = score[i];
    g_order[rank] = i;
    g_ssort[rank] = s;

    const float4 b = *reinterpret_cast<const float4*>(box + (size_t)i * 16);
    const float hw = __fmul_rn(b.z, 0.5f);
    const float hh = __fmul_rn(b.w, 0.5f);
    const float x1 = __fsub_rn(b.x, hw);
    const float y1 = __fsub_rn(b.y, hh);
    const float x2 = __fadd_rn(b.x, hw);
    const float y2 = __fadd_rn(b.y, hh);
    g_sxyxy[rank] = make_float4(x1, y1, x2, y2);
    g_sarea[rank] = __fmul_rn(__fsub_rn(x2, x1), __fsub_rn(y2, y1));

    if (s >= MIN_SCORE) atomicOr(&g_valid[rank >> 5], 1u << (rank & 31));
}

// ---------------------------------------------------------------------------
// Suppression matrix: g_mask[i] bit j = (IoU(i,j) > thr).  Upper triangle
// only; stale lower-triangle words are never consulted by the scan.
// ---------------------------------------------------------------------------
__global__ __launch_bounds__(256) void mask_kernel()
{
    const int cc = blockIdx.x;             // col chunk of 1024
    const int rb = blockIdx.y;             // row block of 256
    if ((cc + 1) * 1024 <= rb * 256) return;

    __shared__ float4 sxy[1024];
    __shared__ float  sar[1024];
    const int jbase = cc << 10;
    for (int r = threadIdx.x; r < 1024; r += 256) {
        sxy[r] = g_sxyxy[jbase + r];
        sar[r] = g_sarea[jbase + r];
    }
    __syncthreads();

    const int w = threadIdx.x >> 5, lane = threadIdx.x & 31;
    const int rowbase = (rb << 8) + (w << 5);
    const int i = rowbase + lane;
    const float4 bi = g_sxyxy[i];
    const float  ai = g_sarea[i];

    int jw0 = (rowbase - jbase) >> 5;
    if (jw0 < 0) jw0 = 0;

    for (int jw = jw0; jw < 32; ++jw) {
        unsigned word = 0;
#pragma unroll 8
        for (int b = 0; b < 32; ++b) {
            const int jl = (jw << 5) + b;
            const float4 bj = sxy[jl];
            const float  aj = sar[jl];
            const float ltx = fmaxf(bi.x, bj.x);
            const float lty = fmaxf(bi.y, bj.y);
            const float rbx = fminf(bi.z, bj.z);
            const float rby = fminf(bi.w, bj.w);
            const float ww = fmaxf(__fsub_rn(rbx, ltx), 0.0f);
            const float hh = fmaxf(__fsub_rn(rby, lty), 0.0f);
            const float inter = __fmul_rn(ww, hh);
            const float den =
                __fadd_rn(__fsub_rn(__fadd_rn(ai, aj), inter), 1e-9f);
            if (inter > __fmul_rn(NMS_THR, den)) word |= (1u << b);
        }
        g_mask[i][(cc << 5) + jw] = word;
    }
}

// ---------------------------------------------------------------------------
// Candidate-batch greedy scan + output (256 threads, 1 block).
// Per batch: enumerate 32 lowest alive ranks; fetch exactly those 32 mask
// rows into smem with a FULLY UNROLLED fetch (32 independent registers ->
// MLP 32, one L2 latency per batch — this is the round-12 fix); resolve the
// 32x32 candidate sub-matrix in warp 0 (REDUX fast path / serial fallback);
// apply accepted rows from smem into the register-distributed acc.
// ---------------------------------------------------------------------------
__global__ __launch_bounds__(256, 1) void scan_out_kernel(const float* __restrict__ box,
                                                          float* __restrict__ out)
{
    __shared__ unsigned s_rows[32][257];   // stride 257 => banks (k+t)%32
    __shared__ unsigned s_alive[NW];
    __shared__ int s_cand[32];             // padded to 32 with duplicates
    __shared__ unsigned s_keptmask;
    __shared__ int s_ncand, s_nk, s_wstart, s_stop;
    __shared__ int s_kept[MAX_OUT];

    const int t = threadIdx.x;
    const unsigned FULL = 0xffffffffu;

    unsigned acc = 0;
    const unsigned validw = g_valid[t];
    if (t == 0) { s_nk = 0; s_wstart = 0; s_stop = 0; }
    __syncthreads();

    while (true) {
        s_alive[t] = validw & ~acc;
        __syncthreads();

        // ---- 1. find up to 32 lowest alive ranks (warp 0), pad to 32
        if (t < 32) {
            int cnt = 0;
            for (int wg = s_wstart >> 5; wg < 8 && cnt < 32; ++wg) {
                unsigned w = s_alive[(wg << 5) + t];
                unsigned bal = __ballot_sync(FULL, w != 0);
                while (bal && cnt < 32) {
                    const int l = __ffs(bal) - 1;
                    unsigned wl = __shfl_sync(FULL, w, l);
                    while (wl && cnt < 32) {
                        const int b = __ffs(wl) - 1;
                        wl &= wl - 1u;
                        if (t == 0) s_cand[cnt] = (((wg << 5) + l) << 5) + b;
                        ++cnt;
                    }
                    if (wl) break;
                    bal &= ~(1u << l);
                }
            }
            if (t == 0) {
                s_ncand = cnt;
                for (int k = cnt; k < 32; ++k) s_cand[k] = s_cand[0];  // pad
            }
        }
        __syncthreads();

        const int ncand = s_ncand;
        if (ncand == 0) break;

        // ---- 2. fetch 32 candidate rows — fully unrolled => 32 regs => MLP
        {
            int c[32];
#pragma unroll
            for (int k = 0; k < 32; ++k) c[k] = s_cand[k];
            unsigned v[32];
#pragma unroll
            for (int k = 0; k < 32; ++k) v[k] = g_mask[c[k]][t];
#pragma unroll
            for (int k = 0; k < 32; ++k) s_rows[k][t] = v[k];
        }
        __syncthreads();

        // ---- 3. resolve (warp 0)
        if (t < 32) {
            const unsigned candmask = (ncand == 32) ? FULL : ((1u << ncand) - 1u);
            unsigned B = 0;                       // bit j: cand t suppresses cand j
#pragma unroll
            for (int j = 0; j < 32; ++j) {
                const int r = s_cand[j];
                B |= ((s_rows[t][r >> 5] >> (r & 31)) & 1u) << j;
            }
            B &= candmask;                        // padding lanes' bits are garbage
            if (t >= ncand) B = 0;

            const unsigned above = ~((2u << t) - 1u);      // t=31 -> 0
            const unsigned bad = __reduce_or_sync(FULL, B & above);

            unsigned kept;
            if (bad == 0) {
                kept = candmask;                  // fast path: mutually disjoint
            } else {
                unsigned cur = candmask; kept = 0;
                while (cur) {                     // exact serial greedy
                    const int i = __ffs(cur) - 1;
                    kept |= 1u << i;
                    const unsigned row = __shfl_sync(FULL, B, i);
                    cur &= ~(1u << i);
                    cur &= ~row;
                }
            }

            int nk = s_nk;
            if ((kept >> t) & 1u) {
                const int pos = nk + __popc(kept & ((1u << t) - 1u));
                if (pos < MAX_OUT) s_kept[pos] = s_cand[t];
            }
            nk += __popc(kept);
            if (nk >= MAX_OUT) { nk = MAX_OUT; if (t == 0) s_stop = 1; }
            if (t == 0) {
                s_nk = nk;
                s_keptmask = kept;
                s_wstart = s_cand[ncand - 1] >> 5;   // monotone frontier
            }
        }
        __syncthreads();

        if (s_stop) break;                        // uniform

        // ---- 4. apply accepted rows (conflict-free LDS, banks (k+t)%32)
        unsigned km = s_keptmask, orv = 0;
        while (km) {
            const int k = __ffs(km) - 1;
            km &= km - 1u;
            orv |= s_rows[k][t];
        }
        acc |= orv;
        // explicitly retire all candidates (kept: self-bit safety for
        // degenerate boxes; suppressed: covered by accepted rows anyway)
        unsigned km2 = s_keptmask;
        while (km2) {
            const int k = __ffs(km2) - 1;
            km2 &= km2 - 1u;
            const int r = s_cand[k];
            if ((r >> 5) == t) acc |= 1u << (r & 31);
        }
        // loop-top barrier orders this against the next batch
    }
    __syncthreads();

    const int nkf = s_nk;

    // Output: [score(256) | box(256x16) | valid(256)] as float32.
    float4 vb0 = make_float4(0.f, 0.f, 0.f, 0.f), vb1 = vb0, vb2 = vb0, vb3 = vb0;
    float sc = 0.0f, vl = 0.0f;
    if (t < nkf) {
        const int si = s_kept[t];
        const int orig = g_order[si];
        const float4* bp = reinterpret_cast<const float4*>(box + (size_t)orig * 16);
        vb0 = bp[0]; vb1 = bp[1]; vb2 = bp[2]; vb3 = bp[3];
        sc = g_ssort[si];
        vl = 1.0f;
    }
    float4* op = reinterpret_cast<float4*>(out + 256 + t * 16);
    op[0] = vb0; op[1] = vb1; op[2] = vb2; op[3] = vb3;
    out[t] = sc;
    out[4352 + t] = vl;
}

extern "C" void kernel_launch(void* const* d_in, const int* in_sizes, int n_in,
                              void* d_out, int out_size)
{
    (void)in_sizes; (void)n_in; (void)out_size;
    const float* score = (const float*)d_in[0];
    const float* box   = (const float*)d_in[1];
    float* out = (float*)d_out;

    rank_partial_kernel<<<dim3(64, 8), 128>>>(score);
    rank_scatter_kernel<<<32, 256>>>(score, box);
    mask_kernel<<<dim3(8, 32), 256>>>();
    scan_out_kernel<<<1, 256>>>(box, out);
}

// round 17
// speedup vs baseline: 1.6642x; 1.0793x over previous
#include <cuda_runtime.h>

#define N 8192
#define NW 256            // 32-bit words per mask row (8192/32)
#define MIN_SCORE 0.3f
#define NMS_THR 0.3f
#define MAX_OUT 256

// scratch (no allocations allowed; zero-initialized at module load)
__device__ int      g_order[N];
__device__ float    g_ssort[N];
__device__ unsigned g_partial[8][N];
__device__ float4   g_sxyxy[N];       // sorted-order xyxy
__device__ float    g_sarea[N];       // sorted-order area
__device__ unsigned g_valid[NW];      // score >= MIN_SCORE, by sorted rank
__device__ unsigned g_mask[N][NW];    // suppression matrix, 8MB (L2-resident)

// ---------------------------------------------------------------------------
// Rank sort, stage 1: partial ranks over a 1024-wide j-tile per block.
// rank(i) = #{j<i : s_j >= s_i} + #{j>=i : s_j > s_i}
// (exactly matches stable argsort(-s): ties broken by ascending index)
// ---------------------------------------------------------------------------
__global__ __launch_bounds__(128) void rank_partial_kernel(const float* __restrict__ score)
{
    __shared__ float sh[1024];
    const int jlo = blockIdx.y << 10;
    for (int r = threadIdx.x; r < 1024; r += 128) sh[r] = score[jlo + r];
    if (blockIdx.x == 0 && blockIdx.y == 0) {
        g_valid[threadIdx.x] = 0;
        g_valid[threadIdx.x + 128] = 0;
    }
    __syncthreads();

    const int i = blockIdx.x * 128 + threadIdx.x;
    const float si = score[i];

    int m = i - jlo;                    // local j < m  <=>  global j < i
    m = m < 0 ? 0 : (m > 1024 ? 1024 : m);

    int cnt = 0;
    const float4* sh4 = reinterpret_cast<const float4*>(sh);

    const int m4 = m >> 2;
    for (int q = 0; q < m4; ++q) {
        float4 v = sh4[q];
        cnt += (v.x >= si) + (v.y >= si) + (v.z >= si) + (v.w >= si);
    }
    for (int r = m4 << 2; r < m; ++r) cnt += (sh[r] >= si);

    const int q0 = (m + 3) >> 2;
    int rend = q0 << 2; if (rend > 1024) rend = 1024;
    for (int r = m; r < rend; ++r) cnt += (sh[r] > si);
    for (int q = q0; q < 256; ++q) {
        float4 v = sh4[q];
        cnt += (v.x > si) + (v.y > si) + (v.z > si) + (v.w > si);
    }

    g_partial[blockIdx.y][i] = (unsigned)cnt;
}

// ---------------------------------------------------------------------------
// Stage 2: combine partials; scatter index/score/xyxy/area into sorted rank;
// build the valid bitmask.
// ---------------------------------------------------------------------------
__global__ __launch_bounds__(256) void rank_scatter_kernel(const float* __restrict__ score,
                                                           const float* __restrict__ box)
{
    const int i = blockIdx.x * 256 + threadIdx.x;
    unsigned rank = 0;
#pragma unroll
    for (int k = 0; k < 8; ++k) rank += g_partial[k][i];

    const float s = score[i];
    g_order[rank] = i;
    g_ssort[rank] = s;

    const float4 b = *reinterpret_cast<const float4*>(box + (size_t)i * 16);
    const float hw = __fmul_rn(b.z, 0.5f);
    const float hh = __fmul_rn(b.w, 0.5f);
    const float x1 = __fsub_rn(b.x, hw);
    const float y1 = __fsub_rn(b.y, hh);
    const float x2 = __fadd_rn(b.x, hw);
    const float y2 = __fadd_rn(b.y, hh);
    g_sxyxy[rank] = make_float4(x1, y1, x2, y2);
    g_sarea[rank] = __fmul_rn(__fsub_rn(x2, x1), __fsub_rn(y2, y1));

    if (s >= MIN_SCORE) atomicOr(&g_valid[rank >> 5], 1u << (rank & 31));
}

// ---------------------------------------------------------------------------
// Suppression matrix: g_mask[i] bit j = (IoU(i,j) > thr).  Upper triangle
// only; stale lower-triangle words are never consulted by the scan.
// ---------------------------------------------------------------------------
__global__ __launch_bounds__(256) void mask_kernel()
{
    const int cc = blockIdx.x;             // col chunk of 1024
    const int rb = blockIdx.y;             // row block of 256
    if ((cc + 1) * 1024 <= rb * 256) return;

    __shared__ float4 sxy[1024];
    __shared__ float  sar[1024];
    const int jbase = cc << 10;
    for (int r = threadIdx.x; r < 1024; r += 256) {
        sxy[r] = g_sxyxy[jbase + r];
        sar[r] = g_sarea[jbase + r];
    }
    __syncthreads();

    const int w = threadIdx.x >> 5, lane = threadIdx.x & 31;
    const int rowbase = (rb << 8) + (w << 5);
    const int i = rowbase + lane;
    const float4 bi = g_sxyxy[i];
    const float  ai = g_sarea[i];

    int jw0 = (rowbase - jbase) >> 5;
    if (jw0 < 0) jw0 = 0;

    for (int jw = jw0; jw < 32; ++jw) {
        unsigned word = 0;
#pragma unroll 8
        for (int b = 0; b < 32; ++b) {
            const int jl = (jw << 5) + b;
            const float4 bj = sxy[jl];
            const float  aj = sar[jl];
            const float ltx = fmaxf(bi.x, bj.x);
            const float lty = fmaxf(bi.y, bj.y);
            const float rbx = fminf(bi.z, bj.z);
            const float rby = fminf(bi.w, bj.w);
            const float ww = fmaxf(__fsub_rn(rbx, ltx), 0.0f);
            const float hh = fmaxf(__fsub_rn(rby, lty), 0.0f);
            const float inter = __fmul_rn(ww, hh);
            const float den =
                __fadd_rn(__fsub_rn(__fadd_rn(ai, aj), inter), 1e-9f);
            if (inter > __fmul_rn(NMS_THR, den)) word |= (1u << b);
        }
        g_mask[i][(cc << 5) + jw] = word;
    }
}

// ---------------------------------------------------------------------------
// Candidate-batch greedy scan + output (256 threads, 1 block).
// Per batch: enumerate 32 lowest alive ranks; fetch exactly those 32 mask
// rows into smem in two unrolled halves of 16 (16+16 regs live -> NO SPILLS,
// MLP 16 per wave — this is the round-13 fix); resolve the 32x32 candidate
// sub-matrix in warp 0; apply accepted rows via unrolled predicated LDS.
// ---------------------------------------------------------------------------
__global__ __launch_bounds__(256, 1) void scan_out_kernel(const float* __restrict__ box,
                                                          float* __restrict__ out)
{
    __shared__ unsigned s_rows[32][257];   // stride 257 => banks (k+t)%32
    __shared__ unsigned s_alive[NW];
    __shared__ int s_cand[32];             // padded to 32 with duplicates
    __shared__ unsigned s_keptmask;
    __shared__ int s_ncand, s_nk, s_wstart, s_stop;
    __shared__ int s_kept[MAX_OUT];

    const int t = threadIdx.x;
    const unsigned FULL = 0xffffffffu;

    unsigned acc = 0;
    const unsigned validw = g_valid[t];
    if (t == 0) { s_nk = 0; s_wstart = 0; s_stop = 0; }
    __syncthreads();

    while (true) {
        s_alive[t] = validw & ~acc;
        __syncthreads();

        // ---- 1. find up to 32 lowest alive ranks (warp 0), pad to 32
        if (t < 32) {
            int cnt = 0;
            for (int wg = s_wstart >> 5; wg < 8 && cnt < 32; ++wg) {
                unsigned w = s_alive[(wg << 5) + t];
                unsigned bal = __ballot_sync(FULL, w != 0);
                while (bal && cnt < 32) {
                    const int l = __ffs(bal) - 1;
                    unsigned wl = __shfl_sync(FULL, w, l);
                    while (wl && cnt < 32) {
                        const int b = __ffs(wl) - 1;
                        wl &= wl - 1u;
                        if (t == 0) s_cand[cnt] = (((wg << 5) + l) << 5) + b;
                        ++cnt;
                    }
                    if (wl) break;
                    bal &= ~(1u << l);
                }
            }
            if (t == 0) {
                s_ncand = cnt;
                for (int k = cnt; k < 32; ++k) s_cand[k] = s_cand[0];  // pad
            }
        }
        __syncthreads();

        const int ncand = s_ncand;
        if (ncand == 0) break;

        // ---- 2. fetch 32 candidate rows in two halves of 16 (no spills)
#pragma unroll
        for (int h = 0; h < 2; ++h) {
            int c[16];
#pragma unroll
            for (int k = 0; k < 16; ++k) c[k] = s_cand[(h << 4) + k];
            unsigned v[16];
#pragma unroll
            for (int k = 0; k < 16; ++k) v[k] = g_mask[c[k]][t];
#pragma unroll
            for (int k = 0; k < 16; ++k) s_rows[(h << 4) + k][t] = v[k];
        }
        __syncthreads();

        // ---- 3. resolve (warp 0)
        if (t < 32) {
            const unsigned candmask = (ncand == 32) ? FULL : ((1u << ncand) - 1u);
            unsigned B = 0;                       // bit j: cand t suppresses cand j
#pragma unroll
            for (int j = 0; j < 32; ++j) {
                const int r = s_cand[j];
                B |= ((s_rows[t][r >> 5] >> (r & 31)) & 1u) << j;
            }
            B &= candmask;                        // padding lanes' bits are garbage
            if (t >= ncand) B = 0;

            const unsigned above = ~((2u << t) - 1u);      // t=31 -> 0
            const unsigned bad = __reduce_or_sync(FULL, B & above);

            unsigned kept;
            if (bad == 0) {
                kept = candmask;                  // fast path: mutually disjoint
            } else {
                unsigned cur = candmask; kept = 0;
                while (cur) {                     // exact serial greedy
                    const int i = __ffs(cur) - 1;
                    kept |= 1u << i;
                    const unsigned row = __shfl_sync(FULL, B, i);
                    cur &= ~(1u << i);
                    cur &= ~row;
                }
            }

            int nk = s_nk;
            if ((kept >> t) & 1u) {
                const int pos = nk + __popc(kept & ((1u << t) - 1u));
                if (pos < MAX_OUT) s_kept[pos] = s_cand[t];
            }
            nk += __popc(kept);
            if (nk >= MAX_OUT) { nk = MAX_OUT; if (t == 0) s_stop = 1; }
            if (t == 0) {
                s_nk = nk;
                s_keptmask = kept;
                s_wstart = s_cand[ncand - 1] >> 5;   // monotone frontier
            }
        }
        __syncthreads();

        if (s_stop) break;                        // uniform

        // ---- 4. apply accepted rows: unrolled predicated LDS (pipelined)
        {
            const unsigned kept = s_keptmask;
            unsigned orv = 0;
#pragma unroll
            for (int k = 0; k < 32; ++k)
                if ((kept >> k) & 1u) orv |= s_rows[k][t];
            acc |= orv;
            // explicitly retire accepted candidates (self-bit safety for
            // degenerate zero-area boxes whose self-IoU is 0)
#pragma unroll
            for (int k = 0; k < 32; ++k) {
                if ((kept >> k) & 1u) {
                    const int r = s_cand[k];      // warp-uniform LDS broadcast
                    if ((r >> 5) == t) acc |= 1u << (r & 31);
                }
            }
        }
        // loop-top barrier orders this against the next batch
    }
    __syncthreads();

    const int nkf = s_nk;

    // Output: [score(256) | box(256x16) | valid(256)] as float32.
    float4 vb0 = make_float4(0.f, 0.f, 0.f, 0.f), vb1 = vb0, vb2 = vb0, vb3 = vb0;
    float sc = 0.0f, vl = 0.0f;
    if (t < nkf) {
        const int si = s_kept[t];
        const int orig = g_order[si];
        const float4* bp = reinterpret_cast<const float4*>(box + (size_t)orig * 16);
        vb0 = bp[0]; vb1 = bp[1]; vb2 = bp[2]; vb3 = bp[3];
        sc = g_ssort[si];
        vl = 1.0f;
    }
    float4* op = reinterpret_cast<float4*>(out + 256 + t * 16);
    op[0] = vb0; op[1] = vb1; op[2] = vb2; op[3] = vb3;
    out[t] = sc;
    out[4352 + t] = vl;
}

extern "C" void kernel_launch(void* const* d_in, const int* in_sizes, int n_in,
                              void* d_out, int out_size)
{
    (void)in_sizes; (void)n_in; (void)out_size;
    const float* score = (const float*)d_in[0];
    const float* box   = (const float*)d_in[1];
    float* out = (float*)d_out;

    rank_partial_kernel<<<dim3(64, 8), 128>>>(score);
    rank_scatter_kernel<<<32, 256>>>(score, box);
    mask_kernel<<<dim3(8, 32), 256>>>();
    scan_out_kernel<<<1, 256>>>(box, out);
}